// round 10
// baseline (speedup 1.0000x reference)
#include <cuda_runtime.h>
#include <cstdint>

// Problem constants (B=2, C=1, D=128, H=256, W=256)
#define NVOL   2
#define DD     128
#define HH     256
#define WW     256
#define NB     (NVOL*DD*HH*WW)      // 16,777,216 voxels
#define WPR    (WW/32)              // 8 packed words per row
#define NWORDS (NVOL*DD*HH*WPR)     // 524,288 words (2 MB)
#define PW     10.0

// pass1: 2048 blocks x 256 thr = 524,288 threads -> 8 quads/thread
#define P1_BLOCKS  2048
#define P1_THREADS 256
#define P1_TOTAL   (P1_BLOCKS*P1_THREADS)

// merged dilation kernel: 8 outputs/thread/phase -> 65,536 threads
#define DL_THREADS 128
#define DL_BLOCKS  ((NWORDS / 8) / DL_THREADS)   // 512 (all co-resident)

// Scratch (allocation-free __device__ globals; zero-initialized at load)
__device__ unsigned int g_mask[NWORDS];
__device__ unsigned int g_tmp[NWORDS];
__device__ double g_base;      // sum |t-i| over all voxels
__device__ double g_corr;      // sum |t-i| over NOT-dilated voxels
__device__ unsigned int g_bcount;
__device__ volatile unsigned int g_sync;   // software grid barrier counter

// ---------------------------------------------------------------------------
// Pass 1: single streaming read of input+target (128 MB).
// Emits base = sum|t-i| and packed support mask (0 < t < 1).
// ---------------------------------------------------------------------------
__global__ void __launch_bounds__(P1_THREADS) pass1_kernel(
        const float4* __restrict__ inp,
        const float4* __restrict__ tgt) {
    int tid = blockIdx.x * blockDim.x + threadIdx.x;
    float base = 0.0f;

    #pragma unroll
    for (int g = 0; g < 2; ++g) {
        float4 a[4], b[4];
        int i0 = tid + g * 4 * P1_TOTAL;
        #pragma unroll
        for (int k = 0; k < 4; ++k) {
            int i = i0 + k * P1_TOTAL;
            a[k] = __ldcs(inp + i);
            b[k] = __ldcs(tgt + i);
        }
        #pragma unroll
        for (int k = 0; k < 4; ++k) {
            int i = i0 + k * P1_TOTAL;
            float dx = fabsf(b[k].x - a[k].x);
            float dy = fabsf(b[k].y - a[k].y);
            float dz = fabsf(b[k].z - a[k].z);
            float dw = fabsf(b[k].w - a[k].w);
            base += (dx + dy) + (dz + dw);

            unsigned nib =
                (unsigned)(b[k].x > 0.0f && b[k].x < 1.0f)
              | ((unsigned)(b[k].y > 0.0f && b[k].y < 1.0f) << 1)
              | ((unsigned)(b[k].z > 0.0f && b[k].z < 1.0f) << 2)
              | ((unsigned)(b[k].w > 0.0f && b[k].w < 1.0f) << 3);
            // 8 consecutive threads' nibbles -> one 32-bit word
            unsigned p  = nib | (__shfl_down_sync(0xFFFFFFFFu, nib, 1) << 4);
            unsigned p2 = p   | (__shfl_down_sync(0xFFFFFFFFu, p,   2) << 8);
            unsigned w  = p2  | (__shfl_down_sync(0xFFFFFFFFu, p2,  4) << 16);
            if ((threadIdx.x & 7) == 0) g_mask[i >> 3] = w;
        }
    }

    #pragma unroll
    for (int off = 16; off > 0; off >>= 1)
        base += __shfl_down_sync(0xFFFFFFFFu, base, off);
    __shared__ float ws[P1_THREADS / 32];
    int lane = threadIdx.x & 31, wid = threadIdx.x >> 5;
    if (lane == 0) ws[wid] = base;
    __syncthreads();
    if (wid == 0) {
        float s = (lane < P1_THREADS / 32) ? ws[lane] : 0.0f;
        #pragma unroll
        for (int off = 4; off > 0; off >>= 1)
            s += __shfl_down_sync(0xFFFFFFFFu, s, off);
        if (lane == 0) atomicAdd(&g_base, (double)s);
    }
}

// horizontal (x) dilation by +-3 bits across word boundaries
__device__ __forceinline__ unsigned hdil3(unsigned prev, unsigned cur, unsigned next) {
    unsigned r = cur;
    r |= __funnelshift_l(prev, cur, 1);
    r |= __funnelshift_l(prev, cur, 2);
    r |= __funnelshift_l(prev, cur, 3);
    r |= __funnelshift_r(cur, next, 1);
    r |= __funnelshift_r(cur, next, 2);
    r |= __funnelshift_r(cur, next, 3);
    return r;
}

// sliding OR of width 7 over win[0..13] -> out[0..7] using suffix/prefix split
__device__ __forceinline__ void slide_or7(const unsigned* win, unsigned* out) {
    unsigned suf[7], pre[7];
    suf[6] = win[6];
    #pragma unroll
    for (int i = 5; i >= 0; --i) suf[i] = win[i] | suf[i + 1];
    pre[0] = win[7];
    #pragma unroll
    for (int j = 1; j < 7; ++j) pre[j] = pre[j - 1] | win[7 + j];
    out[0] = suf[0];
    #pragma unroll
    for (int k = 1; k < 7; ++k) out[k] = suf[k] | pre[k - 1];
    out[7] = pre[6];                     // window lies entirely in prefix side
}

// ---------------------------------------------------------------------------
// Merged dilation: phase XY (g_mask -> g_tmp), software grid barrier,
// phase Z (7-z OR) + complement correction + finalize.
//   loss = 11*base - 10*corr ; out = loss/NB written by the last block.
// All DL_BLOCKS blocks are co-resident (128 thr, 512 blocks on 148 SMs),
// so the spin barrier cannot deadlock.
// ---------------------------------------------------------------------------
__global__ void __launch_bounds__(DL_THREADS) dilate_corr_kernel(
        const float* __restrict__ inp,
        const float* __restrict__ tgt,
        float* __restrict__ out) {
    int t = blockIdx.x * blockDim.x + threadIdx.x;    // 65536 threads

    // ---- Phase XY: x+y dilation, 8 y-outputs per thread ----
    {
        int wx = t & 7;
        int yg = (t >> 3) & 31;                       // 32 groups of 8 rows
        int vz = t >> 8;                              // v*DD+z, 0..255
        int rowbase = vz << 11;
        int y0 = yg << 3;

        unsigned hr[14];
        #pragma unroll
        for (int r = 0; r < 14; ++r) {
            int yy = y0 - 3 + r;
            if ((unsigned)yy >= HH) { hr[r] = 0u; continue; }
            int base = rowbase + (yy << 3);
            unsigned cur  = g_mask[base + wx];
            unsigned prev = (wx > 0) ? g_mask[base + wx - 1] : 0u;
            unsigned next = (wx < 7) ? g_mask[base + wx + 1] : 0u;
            hr[r] = hdil3(prev, cur, next);
        }
        unsigned outw[8];
        slide_or7(hr, outw);
        #pragma unroll
        for (int k = 0; k < 8; ++k)
            g_tmp[rowbase + ((y0 + k) << 3) + wx] = outw[k];
    }

    // ---- software grid barrier (all blocks co-resident) ----
    __threadfence();
    __syncthreads();
    if (threadIdx.x == 0) {
        atomicAdd((unsigned*)&g_sync, 1u);
        while (g_sync < (unsigned)gridDim.x) { }
    }
    __syncthreads();

    // ---- Phase Z: z dilation + complement correction ----
    float corr = 0.0f;
    {
        int wxy = t & 2047;                           // word within z-slice
        int zg  = (t >> 11) & 15;                     // 16 groups of 8 z
        int v   = t >> 15;
        int z0  = zg << 3;

        unsigned c[14];
        #pragma unroll
        for (int r = 0; r < 14; ++r) {
            int zz = z0 - 3 + r;
            c[r] = ((unsigned)zz < DD) ? g_tmp[(((v << 7) + zz) << 11) + wxy] : 0u;
        }
        unsigned res[8];
        slide_or7(c, res);

        #pragma unroll
        for (int k = 0; k < 8; ++k) {
            unsigned miss = ~res[k];                  // unweighted voxels
            if (miss) {
                int wordidx = (((v << 7) + (z0 + k)) << 11) + wxy;
                int vox0 = wordidx << 5;
                do {
                    int bit = __ffs(miss) - 1;
                    miss &= miss - 1u;
                    int i = vox0 + bit;
                    corr += fabsf(tgt[i] - inp[i]);
                } while (miss);
            }
        }
    }

    // ---- reduce + finalize ----
    #pragma unroll
    for (int off = 16; off > 0; off >>= 1)
        corr += __shfl_down_sync(0xFFFFFFFFu, corr, off);
    __shared__ float ws[DL_THREADS / 32];
    int lane = threadIdx.x & 31, wid = threadIdx.x >> 5;
    if (lane == 0) ws[wid] = corr;
    __syncthreads();
    if (wid == 0) {
        float s = (lane < DL_THREADS / 32) ? ws[lane] : 0.0f;
        #pragma unroll
        for (int off = 2; off > 0; off >>= 1)
            s += __shfl_down_sync(0xFFFFFFFFu, s, off);
        if (lane == 0) {
            atomicAdd(&g_corr, (double)s);
            __threadfence();
            unsigned prev = atomicAdd(&g_bcount, 1u);
            if (prev == gridDim.x - 1) {
                double total = (1.0 + PW) * g_base - PW * g_corr;
                out[0] = (float)(total / (double)NB);
                g_base = 0.0;        // reset for next graph replay
                g_corr = 0.0;
                g_bcount = 0u;
                g_sync = 0u;         // reset barrier (all blocks already passed)
            }
        }
    }
}

extern "C" void kernel_launch(void* const* d_in, const int* in_sizes, int n_in,
                              void* d_out, int out_size) {
    const float* inp = (const float*)d_in[0];
    const float* tgt = (const float*)d_in[1];
    float* out = (float*)d_out;

    pass1_kernel<<<P1_BLOCKS, P1_THREADS>>>((const float4*)inp, (const float4*)tgt);
    dilate_corr_kernel<<<DL_BLOCKS, DL_THREADS>>>(inp, tgt, out);
}

// round 11
// speedup vs baseline: 1.1220x; 1.1220x over previous
#include <cuda_runtime.h>
#include <cstdint>

// Problem constants (B=2, C=1, D=128, H=256, W=256)
#define NVOL   2
#define DD     128
#define HH     256
#define WW     256
#define NB     (NVOL*DD*HH*WW)      // 16,777,216 voxels
#define WPR    (WW/32)              // 8 packed words per row
#define NWORDS (NVOL*DD*HH*WPR)     // 524,288 words (2 MB)
#define PW     10.0

// pass1: 2048 blocks x 256 thr = 524,288 threads -> 8 quads/thread
#define P1_BLOCKS  2048
#define P1_THREADS 256
#define P1_TOTAL   (P1_BLOCKS*P1_THREADS)

// dilation kernels: 8 outputs/thread -> 65,536 threads each
#define XY_THREADS 128
#define XY_BLOCKS  ((NWORDS / 8) / XY_THREADS)   // 512
#define DZ_THREADS 128
#define DZ_BLOCKS  ((NWORDS / 8) / DZ_THREADS)   // 512

// Scratch (allocation-free __device__ globals; zero-initialized at load)
__device__ unsigned int g_mask[NWORDS];
__device__ unsigned int g_tmp[NWORDS];
__device__ double g_base;      // sum |t-i| over all voxels
__device__ double g_corr;      // sum |t-i| over NOT-dilated voxels
__device__ unsigned int g_bcount;

// ---------------------------------------------------------------------------
// Pass 1: single streaming read of input+target (128 MB).
// Emits base = sum|t-i| and packed support mask (0 < t < 1).
// ---------------------------------------------------------------------------
__global__ void __launch_bounds__(P1_THREADS) pass1_kernel(
        const float4* __restrict__ inp,
        const float4* __restrict__ tgt) {
    int tid = blockIdx.x * blockDim.x + threadIdx.x;
    float base = 0.0f;

    #pragma unroll
    for (int g = 0; g < 2; ++g) {
        float4 a[4], b[4];
        int i0 = tid + g * 4 * P1_TOTAL;
        #pragma unroll
        for (int k = 0; k < 4; ++k) {
            int i = i0 + k * P1_TOTAL;
            a[k] = __ldcs(inp + i);
            b[k] = __ldcs(tgt + i);
        }
        #pragma unroll
        for (int k = 0; k < 4; ++k) {
            int i = i0 + k * P1_TOTAL;
            float dx = fabsf(b[k].x - a[k].x);
            float dy = fabsf(b[k].y - a[k].y);
            float dz = fabsf(b[k].z - a[k].z);
            float dw = fabsf(b[k].w - a[k].w);
            base += (dx + dy) + (dz + dw);

            unsigned nib =
                (unsigned)(b[k].x > 0.0f && b[k].x < 1.0f)
              | ((unsigned)(b[k].y > 0.0f && b[k].y < 1.0f) << 1)
              | ((unsigned)(b[k].z > 0.0f && b[k].z < 1.0f) << 2)
              | ((unsigned)(b[k].w > 0.0f && b[k].w < 1.0f) << 3);
            // 8 consecutive threads' nibbles -> one 32-bit word
            unsigned p  = nib | (__shfl_down_sync(0xFFFFFFFFu, nib, 1) << 4);
            unsigned p2 = p   | (__shfl_down_sync(0xFFFFFFFFu, p,   2) << 8);
            unsigned w  = p2  | (__shfl_down_sync(0xFFFFFFFFu, p2,  4) << 16);
            if ((threadIdx.x & 7) == 0) g_mask[i >> 3] = w;
        }
    }

    #pragma unroll
    for (int off = 16; off > 0; off >>= 1)
        base += __shfl_down_sync(0xFFFFFFFFu, base, off);
    __shared__ float ws[P1_THREADS / 32];
    int lane = threadIdx.x & 31, wid = threadIdx.x >> 5;
    if (lane == 0) ws[wid] = base;
    __syncthreads();
    if (wid == 0) {
        float s = (lane < P1_THREADS / 32) ? ws[lane] : 0.0f;
        #pragma unroll
        for (int off = 4; off > 0; off >>= 1)
            s += __shfl_down_sync(0xFFFFFFFFu, s, off);
        if (lane == 0) atomicAdd(&g_base, (double)s);
    }
}

// horizontal (x) dilation by +-3 bits across word boundaries
__device__ __forceinline__ unsigned hdil3(unsigned prev, unsigned cur, unsigned next) {
    unsigned r = cur;
    r |= __funnelshift_l(prev, cur, 1);
    r |= __funnelshift_l(prev, cur, 2);
    r |= __funnelshift_l(prev, cur, 3);
    r |= __funnelshift_r(cur, next, 1);
    r |= __funnelshift_r(cur, next, 2);
    r |= __funnelshift_r(cur, next, 3);
    return r;
}

// sliding OR of width 7 over win[0..13] -> out[0..7] using suffix/prefix split
__device__ __forceinline__ void slide_or7(const unsigned* win, unsigned* out) {
    unsigned suf[7], pre[7];
    suf[6] = win[6];
    #pragma unroll
    for (int i = 5; i >= 0; --i) suf[i] = win[i] | suf[i + 1];
    pre[0] = win[7];
    #pragma unroll
    for (int j = 1; j < 7; ++j) pre[j] = pre[j - 1] | win[7 + j];
    out[0] = suf[0];
    #pragma unroll
    for (int k = 1; k < 7; ++k) out[k] = suf[k] | pre[k - 1];
    out[7] = pre[6];                     // window lies entirely in prefix side
}

// ---------------------------------------------------------------------------
// x+y dilation, 8 y-outputs per thread. g_mask -> g_tmp.
// Neighbor words (wx +- 1) come from adjacent lanes via shfl (1 load/row
// instead of 3). Loads are predicated (not branched) so shfl stays uniform.
// ---------------------------------------------------------------------------
__global__ void __launch_bounds__(XY_THREADS) dilate_xy_kernel() {
    cudaGridDependencySynchronize();     // PDL: wait for pass1 completion
    int t = blockIdx.x * blockDim.x + threadIdx.x;    // 65536 threads
    int wx = t & 7;
    int yg = (t >> 3) & 31;                           // 32 groups of 8 rows
    int vz = t >> 8;                                  // v*DD+z, 0..255
    int rowbase = vz << 11;
    int y0 = yg << 3;

    unsigned hr[14];
    #pragma unroll
    for (int r = 0; r < 14; ++r) {
        int yy = y0 - 3 + r;
        unsigned cur = ((unsigned)yy < HH) ? g_mask[rowbase + (yy << 3) + wx] : 0u;
        unsigned prev = __shfl_up_sync(0xFFFFFFFFu, cur, 1);
        unsigned next = __shfl_down_sync(0xFFFFFFFFu, cur, 1);
        if (wx == 0) prev = 0u;
        if (wx == 7) next = 0u;
        hr[r] = hdil3(prev, cur, next);
    }
    unsigned outw[8];
    slide_or7(hr, outw);
    #pragma unroll
    for (int k = 0; k < 8; ++k)
        g_tmp[rowbase + ((y0 + k) << 3) + wx] = outw[k];
}

// ---------------------------------------------------------------------------
// Fused z-dilation (8 z-outputs/thread) + complement correction + finalize.
//   loss = 11*base - 10*corr ; out = loss/NB written by the last block.
// ---------------------------------------------------------------------------
__global__ void __launch_bounds__(DZ_THREADS) dilate_z_corr_kernel(
        const float* __restrict__ inp,
        const float* __restrict__ tgt,
        float* __restrict__ out) {
    cudaGridDependencySynchronize();     // PDL: wait for dilate_xy completion
    int t = blockIdx.x * blockDim.x + threadIdx.x;    // 65536 threads
    int wxy = t & 2047;                               // word within z-slice
    int zg  = (t >> 11) & 15;                         // 16 groups of 8 z
    int v   = t >> 15;
    int z0  = zg << 3;

    unsigned c[14];
    #pragma unroll
    for (int r = 0; r < 14; ++r) {
        int zz = z0 - 3 + r;
        c[r] = ((unsigned)zz < DD) ? g_tmp[(((v << 7) + zz) << 11) + wxy] : 0u;
    }
    unsigned res[8];
    slide_or7(c, res);

    float corr = 0.0f;
    #pragma unroll
    for (int k = 0; k < 8; ++k) {
        unsigned miss = ~res[k];                      // unweighted voxels
        if (miss) {
            int wordidx = (((v << 7) + (z0 + k)) << 11) + wxy;
            int vox0 = wordidx << 5;
            do {
                int bit = __ffs(miss) - 1;
                miss &= miss - 1u;
                int i = vox0 + bit;
                corr += fabsf(tgt[i] - inp[i]);
            } while (miss);
        }
    }

    #pragma unroll
    for (int off = 16; off > 0; off >>= 1)
        corr += __shfl_down_sync(0xFFFFFFFFu, corr, off);
    __shared__ float ws[DZ_THREADS / 32];
    int lane = threadIdx.x & 31, wid = threadIdx.x >> 5;
    if (lane == 0) ws[wid] = corr;
    __syncthreads();
    if (wid == 0) {
        float s = (lane < DZ_THREADS / 32) ? ws[lane] : 0.0f;
        #pragma unroll
        for (int off = 2; off > 0; off >>= 1)
            s += __shfl_down_sync(0xFFFFFFFFu, s, off);
        if (lane == 0) {
            atomicAdd(&g_corr, (double)s);
            __threadfence();
            unsigned prev = atomicAdd(&g_bcount, 1u);
            if (prev == gridDim.x - 1) {
                double total = (1.0 + PW) * g_base - PW * g_corr;
                out[0] = (float)(total / (double)NB);
                g_base = 0.0;        // reset for next graph replay
                g_corr = 0.0;
                g_bcount = 0u;
            }
        }
    }
}

extern "C" void kernel_launch(void* const* d_in, const int* in_sizes, int n_in,
                              void* d_out, int out_size) {
    const float* inp = (const float*)d_in[0];
    const float* tgt = (const float*)d_in[1];
    float* out = (float*)d_out;

    pass1_kernel<<<P1_BLOCKS, P1_THREADS>>>((const float4*)inp, (const float4*)tgt);

    // Tail kernels with programmatic stream serialization: their launch/ramp
    // overlaps the predecessor; cudaGridDependencySynchronize() in-kernel
    // provides the data dependency.
    cudaLaunchAttribute attrs[1];
    attrs[0].id = cudaLaunchAttributeProgrammaticStreamSerialization;
    attrs[0].val.programmaticStreamSerializationAllowed = 1;

    {
        cudaLaunchConfig_t cfg = {};
        cfg.gridDim  = dim3(XY_BLOCKS, 1, 1);
        cfg.blockDim = dim3(XY_THREADS, 1, 1);
        cfg.attrs = attrs;
        cfg.numAttrs = 1;
        cudaLaunchKernelEx(&cfg, dilate_xy_kernel);
    }
    {
        cudaLaunchConfig_t cfg = {};
        cfg.gridDim  = dim3(DZ_BLOCKS, 1, 1);
        cfg.blockDim = dim3(DZ_THREADS, 1, 1);
        cfg.attrs = attrs;
        cfg.numAttrs = 1;
        cudaLaunchKernelEx(&cfg, dilate_z_corr_kernel, inp, tgt, out);
    }
}

// round 12
// speedup vs baseline: 1.1335x; 1.0103x over previous
#include <cuda_runtime.h>
#include <cstdint>

// Problem constants (B=2, C=1, D=128, H=256, W=256)
#define NVOL   2
#define DD     128
#define HH     256
#define WW     256
#define NB     (NVOL*DD*HH*WW)      // 16,777,216 voxels
#define WPR    (WW/32)              // 8 packed words per row
#define NWORDS (NVOL*DD*HH*WPR)     // 524,288 words (2 MB)
#define PW     10.0

// pass1: 4096 blocks x 256 thr = 1,048,576 threads -> 4 quads/thread
// (one front-batched load group; cross-block pipelining instead of
//  intra-thread group serialization)
#define P1_BLOCKS  4096
#define P1_THREADS 256
#define P1_TOTAL   (P1_BLOCKS*P1_THREADS)

// dilation kernels: 8 outputs/thread -> 65,536 threads each
#define XY_THREADS 128
#define XY_BLOCKS  ((NWORDS / 8) / XY_THREADS)   // 512
#define DZ_THREADS 128
#define DZ_BLOCKS  ((NWORDS / 8) / DZ_THREADS)   // 512

// Scratch (allocation-free __device__ globals; zero-initialized at load)
__device__ unsigned int g_mask[NWORDS];
__device__ unsigned int g_tmp[NWORDS];
__device__ double g_base;      // sum |t-i| over all voxels
__device__ double g_corr;      // sum |t-i| over NOT-dilated voxels
__device__ unsigned int g_bcount;

// ---------------------------------------------------------------------------
// Pass 1: single streaming read of input+target (128 MB).
// Emits base = sum|t-i| and packed support mask (0 < t < 1).
// ---------------------------------------------------------------------------
__global__ void __launch_bounds__(P1_THREADS) pass1_kernel(
        const float4* __restrict__ inp,
        const float4* __restrict__ tgt) {
    int tid = blockIdx.x * blockDim.x + threadIdx.x;
    float base = 0.0f;

    float4 a[4], b[4];
    #pragma unroll
    for (int k = 0; k < 4; ++k) {
        int i = tid + k * P1_TOTAL;
        a[k] = __ldcs(inp + i);
        b[k] = __ldcs(tgt + i);
    }
    #pragma unroll
    for (int k = 0; k < 4; ++k) {
        int i = tid + k * P1_TOTAL;
        float dx = fabsf(b[k].x - a[k].x);
        float dy = fabsf(b[k].y - a[k].y);
        float dz = fabsf(b[k].z - a[k].z);
        float dw = fabsf(b[k].w - a[k].w);
        base += (dx + dy) + (dz + dw);

        unsigned nib =
            (unsigned)(b[k].x > 0.0f && b[k].x < 1.0f)
          | ((unsigned)(b[k].y > 0.0f && b[k].y < 1.0f) << 1)
          | ((unsigned)(b[k].z > 0.0f && b[k].z < 1.0f) << 2)
          | ((unsigned)(b[k].w > 0.0f && b[k].w < 1.0f) << 3);
        // 8 consecutive threads' nibbles -> one 32-bit word
        unsigned p  = nib | (__shfl_down_sync(0xFFFFFFFFu, nib, 1) << 4);
        unsigned p2 = p   | (__shfl_down_sync(0xFFFFFFFFu, p,   2) << 8);
        unsigned w  = p2  | (__shfl_down_sync(0xFFFFFFFFu, p2,  4) << 16);
        if ((threadIdx.x & 7) == 0) g_mask[i >> 3] = w;
    }

    #pragma unroll
    for (int off = 16; off > 0; off >>= 1)
        base += __shfl_down_sync(0xFFFFFFFFu, base, off);
    __shared__ float ws[P1_THREADS / 32];
    int lane = threadIdx.x & 31, wid = threadIdx.x >> 5;
    if (lane == 0) ws[wid] = base;
    __syncthreads();
    if (wid == 0) {
        float s = (lane < P1_THREADS / 32) ? ws[lane] : 0.0f;
        #pragma unroll
        for (int off = 4; off > 0; off >>= 1)
            s += __shfl_down_sync(0xFFFFFFFFu, s, off);
        if (lane == 0) atomicAdd(&g_base, (double)s);
    }
}

// horizontal (x) dilation by +-3 bits across word boundaries
__device__ __forceinline__ unsigned hdil3(unsigned prev, unsigned cur, unsigned next) {
    unsigned r = cur;
    r |= __funnelshift_l(prev, cur, 1);
    r |= __funnelshift_l(prev, cur, 2);
    r |= __funnelshift_l(prev, cur, 3);
    r |= __funnelshift_r(cur, next, 1);
    r |= __funnelshift_r(cur, next, 2);
    r |= __funnelshift_r(cur, next, 3);
    return r;
}

// sliding OR of width 7 over win[0..13] -> out[0..7] using suffix/prefix split
__device__ __forceinline__ void slide_or7(const unsigned* win, unsigned* out) {
    unsigned suf[7], pre[7];
    suf[6] = win[6];
    #pragma unroll
    for (int i = 5; i >= 0; --i) suf[i] = win[i] | suf[i + 1];
    pre[0] = win[7];
    #pragma unroll
    for (int j = 1; j < 7; ++j) pre[j] = pre[j - 1] | win[7 + j];
    out[0] = suf[0];
    #pragma unroll
    for (int k = 1; k < 7; ++k) out[k] = suf[k] | pre[k - 1];
    out[7] = pre[6];                     // window lies entirely in prefix side
}

// ---------------------------------------------------------------------------
// x+y dilation, 8 y-outputs per thread. g_mask -> g_tmp.
// Neighbor words (wx +- 1) come from adjacent lanes via shfl (1 load/row
// instead of 3). Loads are predicated (not branched) so shfl stays uniform.
// ---------------------------------------------------------------------------
__global__ void __launch_bounds__(XY_THREADS) dilate_xy_kernel() {
    cudaGridDependencySynchronize();     // PDL: wait for pass1 completion
    int t = blockIdx.x * blockDim.x + threadIdx.x;    // 65536 threads
    int wx = t & 7;
    int yg = (t >> 3) & 31;                           // 32 groups of 8 rows
    int vz = t >> 8;                                  // v*DD+z, 0..255
    int rowbase = vz << 11;
    int y0 = yg << 3;

    unsigned hr[14];
    #pragma unroll
    for (int r = 0; r < 14; ++r) {
        int yy = y0 - 3 + r;
        unsigned cur = ((unsigned)yy < HH) ? g_mask[rowbase + (yy << 3) + wx] : 0u;
        unsigned prev = __shfl_up_sync(0xFFFFFFFFu, cur, 1);
        unsigned next = __shfl_down_sync(0xFFFFFFFFu, cur, 1);
        if (wx == 0) prev = 0u;
        if (wx == 7) next = 0u;
        hr[r] = hdil3(prev, cur, next);
    }
    unsigned outw[8];
    slide_or7(hr, outw);
    #pragma unroll
    for (int k = 0; k < 8; ++k)
        g_tmp[rowbase + ((y0 + k) << 3) + wx] = outw[k];
}

// ---------------------------------------------------------------------------
// Fused z-dilation (8 z-outputs/thread) + complement correction + finalize.
//   loss = 11*base - 10*corr ; out = loss/NB written by the last block.
// ---------------------------------------------------------------------------
__global__ void __launch_bounds__(DZ_THREADS) dilate_z_corr_kernel(
        const float* __restrict__ inp,
        const float* __restrict__ tgt,
        float* __restrict__ out) {
    cudaGridDependencySynchronize();     // PDL: wait for dilate_xy completion
    int t = blockIdx.x * blockDim.x + threadIdx.x;    // 65536 threads
    int wxy = t & 2047;                               // word within z-slice
    int zg  = (t >> 11) & 15;                         // 16 groups of 8 z
    int v   = t >> 15;
    int z0  = zg << 3;

    unsigned c[14];
    #pragma unroll
    for (int r = 0; r < 14; ++r) {
        int zz = z0 - 3 + r;
        c[r] = ((unsigned)zz < DD) ? g_tmp[(((v << 7) + zz) << 11) + wxy] : 0u;
    }
    unsigned res[8];
    slide_or7(c, res);

    float corr = 0.0f;
    #pragma unroll
    for (int k = 0; k < 8; ++k) {
        unsigned miss = ~res[k];                      // unweighted voxels
        if (miss) {
            int wordidx = (((v << 7) + (z0 + k)) << 11) + wxy;
            int vox0 = wordidx << 5;
            do {
                int bit = __ffs(miss) - 1;
                miss &= miss - 1u;
                int i = vox0 + bit;
                corr += fabsf(tgt[i] - inp[i]);
            } while (miss);
        }
    }

    #pragma unroll
    for (int off = 16; off > 0; off >>= 1)
        corr += __shfl_down_sync(0xFFFFFFFFu, corr, off);
    __shared__ float ws[DZ_THREADS / 32];
    int lane = threadIdx.x & 31, wid = threadIdx.x >> 5;
    if (lane == 0) ws[wid] = corr;
    __syncthreads();
    if (wid == 0) {
        float s = (lane < DZ_THREADS / 32) ? ws[lane] : 0.0f;
        #pragma unroll
        for (int off = 2; off > 0; off >>= 1)
            s += __shfl_down_sync(0xFFFFFFFFu, s, off);
        if (lane == 0) {
            atomicAdd(&g_corr, (double)s);
            __threadfence();
            unsigned prev = atomicAdd(&g_bcount, 1u);
            if (prev == gridDim.x - 1) {
                double total = (1.0 + PW) * g_base - PW * g_corr;
                out[0] = (float)(total / (double)NB);
                g_base = 0.0;        // reset for next graph replay
                g_corr = 0.0;
                g_bcount = 0u;
            }
        }
    }
}

extern "C" void kernel_launch(void* const* d_in, const int* in_sizes, int n_in,
                              void* d_out, int out_size) {
    const float* inp = (const float*)d_in[0];
    const float* tgt = (const float*)d_in[1];
    float* out = (float*)d_out;

    pass1_kernel<<<P1_BLOCKS, P1_THREADS>>>((const float4*)inp, (const float4*)tgt);

    // Tail kernels with programmatic stream serialization: their launch/ramp
    // overlaps the predecessor; cudaGridDependencySynchronize() in-kernel
    // provides the data dependency.
    cudaLaunchAttribute attrs[1];
    attrs[0].id = cudaLaunchAttributeProgrammaticStreamSerialization;
    attrs[0].val.programmaticStreamSerializationAllowed = 1;

    {
        cudaLaunchConfig_t cfg = {};
        cfg.gridDim  = dim3(XY_BLOCKS, 1, 1);
        cfg.blockDim = dim3(XY_THREADS, 1, 1);
        cfg.attrs = attrs;
        cfg.numAttrs = 1;
        cudaLaunchKernelEx(&cfg, dilate_xy_kernel);
    }
    {
        cudaLaunchConfig_t cfg = {};
        cfg.gridDim  = dim3(DZ_BLOCKS, 1, 1);
        cfg.blockDim = dim3(DZ_THREADS, 1, 1);
        cfg.attrs = attrs;
        cfg.numAttrs = 1;
        cudaLaunchKernelEx(&cfg, dilate_z_corr_kernel, inp, tgt, out);
    }
}